// round 14
// baseline (speedup 1.0000x reference)
#include <cuda_runtime.h>
#include <cuda_fp16.h>
#include <math.h>
#include <stdint.h>

#define Bc 2
#define Sc 4096
#define Dc 768
#define Hc 12
#define DHc 64
#define Lc 2
#define Fc 3072
#define Cc 256
#define NBc 16
#define NEGF (-1000000000.0f)

// ---------------- scratch (device globals; no allocation allowed) ----------------
__device__ float  g_h  [(size_t)Bc*Sc*Dc];
__device__ __half g_h16[(size_t)Bc*Sc*Dc];
__device__ __half g_q16[(size_t)Bc*Sc*Dc];
__device__ __half g_k16[(size_t)Bc*Sc*Dc];
__device__ __half g_v16[(size_t)Bc*Sc*Dc];
__device__ __half g_ctxh[(size_t)Bc*Sc*Dc];
__device__ float  g_att[(size_t)Bc*Sc*Dc];
__device__ __half g_midh[(size_t)Bc*Sc*Fc];
__device__ __half g_wh [8257536];              // transposed fp16 weights
__device__ float  g_q0 [Bc*Dc];
__device__ float  g_o0 [Bc*Dc];
__device__ float  g_a0 [Bc*Dc];
__device__ float  g_h0 [Bc*Dc];
__device__ float  g_f0 [Bc*Dc];
__device__ float  g_m0 [Bc*Fc];

__device__ __forceinline__ float gelu_exact(float x) {
    return 0.5f * x * (1.0f + erff(x * 0.70710678118654752f));
}

__device__ __forceinline__ void mma_f16(float* c,
    uint32_t a0, uint32_t a1, uint32_t a2, uint32_t a3,
    uint32_t b0, uint32_t b1) {
    asm volatile(
        "mma.sync.aligned.m16n8k16.row.col.f32.f16.f16.f32 "
        "{%0,%1,%2,%3}, {%4,%5,%6,%7}, {%8,%9}, {%0,%1,%2,%3};"
        : "+f"(c[0]), "+f"(c[1]), "+f"(c[2]), "+f"(c[3])
        : "r"(a0), "r"(a1), "r"(a2), "r"(a3), "r"(b0), "r"(b1));
}

__device__ __forceinline__ void cp16(uint32_t s, const void* g) {
    asm volatile("cp.async.cg.shared.global [%0], [%1], 16;" :: "r"(s), "l"(g));
}
#define CP_COMMIT() asm volatile("cp.async.commit_group;")
#define CP_WAIT1()  asm volatile("cp.async.wait_group 1;")

// ---------------- weight transpose+convert: W[K,N] fp32 -> Wh[N,K] fp16 ----------
__global__ void transpose_w(const float* __restrict__ W, __half* __restrict__ Wh,
                            int K, int N) {
    __shared__ float tile[32][33];
    int kb = blockIdx.y*32, nb = blockIdx.x*32;
    int tx = threadIdx.x & 31, ty = threadIdx.x >> 5;
    #pragma unroll
    for (int j = 0; j < 32; j += 8)
        tile[ty+j][tx] = W[(size_t)(kb+ty+j)*N + nb+tx];
    __syncthreads();
    #pragma unroll
    for (int j = 0; j < 32; j += 8)
        Wh[(size_t)(nb+ty+j)*K + kb+tx] = __float2half(tile[tx][ty+j]);
}

// ---------------- fused embedding + LayerNorm ----------------
__global__ void ln_embed_kernel(const int* __restrict__ ids,
                                const float* __restrict__ tok, const float* __restrict__ pos,
                                const float* __restrict__ g, const float* __restrict__ bb,
                                float* __restrict__ out, __half* __restrict__ outh) {
    __shared__ float red[256];
    int row = blockIdx.x, t = threadIdx.x;
    int s = row % Sc;
    const float* tk = tok + (size_t)ids[row]*Dc;
    const float* pp = pos + (size_t)s*Dc;
    float v0 = tk[t]+pp[t], v1 = tk[t+256]+pp[t+256], v2 = tk[t+512]+pp[t+512];
    float sm = v0 + v1 + v2;
    red[t] = sm; __syncthreads();
    for (int o = 128; o > 0; o >>= 1) { if (t < o) red[t] += red[t+o]; __syncthreads(); }
    float mean = red[0] * (1.0f/768.0f); __syncthreads();
    float d0 = v0-mean, d1 = v1-mean, d2 = v2-mean;
    red[t] = d0*d0 + d1*d1 + d2*d2; __syncthreads();
    for (int o = 128; o > 0; o >>= 1) { if (t < o) red[t] += red[t+o]; __syncthreads(); }
    float rstd = rsqrtf(red[0] * (1.0f/768.0f) + 1e-5f);
    float o0 = d0*rstd*g[t]     + bb[t];
    float o1 = d1*rstd*g[t+256] + bb[t+256];
    float o2 = d2*rstd*g[t+512] + bb[t+512];
    float* orow = out + (size_t)row * Dc;
    orow[t] = o0; orow[t+256] = o1; orow[t+512] = o2;
    __half* hrow = outh + (size_t)row * Dc;
    hrow[t] = __float2half(o0); hrow[t+256] = __float2half(o1); hrow[t+512] = __float2half(o2);
}

// ---------------- LayerNorm; residual; optional fp16 second output ------
__global__ void ln_kernel(const float* __restrict__ x, long xs,
                          const float* __restrict__ res, long rs,
                          const float* __restrict__ g, const float* __restrict__ bb,
                          float* __restrict__ out, long os, __half* __restrict__ outh) {
    __shared__ float red[256];
    int row = blockIdx.x, t = threadIdx.x;
    const float* xr = x + (size_t)row * xs;
    float v0 = xr[t], v1 = xr[t+256], v2 = xr[t+512];
    if (res) {
        const float* rr = res + (size_t)row * rs;
        v0 += rr[t]; v1 += rr[t+256]; v2 += rr[t+512];
    }
    float s = v0 + v1 + v2;
    red[t] = s; __syncthreads();
    for (int o = 128; o > 0; o >>= 1) { if (t < o) red[t] += red[t+o]; __syncthreads(); }
    float mean = red[0] * (1.0f/768.0f); __syncthreads();
    float d0 = v0-mean, d1 = v1-mean, d2 = v2-mean;
    red[t] = d0*d0 + d1*d1 + d2*d2; __syncthreads();
    for (int o = 128; o > 0; o >>= 1) { if (t < o) red[t] += red[t+o]; __syncthreads(); }
    float rstd = rsqrtf(red[0] * (1.0f/768.0f) + 1e-5f);
    float o0 = d0*rstd*g[t]     + bb[t];
    float o1 = d1*rstd*g[t+256] + bb[t+256];
    float o2 = d2*rstd*g[t+512] + bb[t+512];
    float* orow = out + (size_t)row * os;
    orow[t] = o0; orow[t+256] = o1; orow[t+512] = o2;
    if (outh) {
        __half* hrow = outh + (size_t)row * os;
        hrow[t] = __float2half(o0); hrow[t+256] = __float2half(o1); hrow[t+512] = __float2half(o2);
    }
}

// ---------------- fp16 GEMM, 64x64 tile, K-tile 64, 3-stage cp.async, seg-fused --
// A [M,K] fp16 row-major; W [N,K] fp16. 128 threads (4 warps 2x2), 4 CTAs/SM.
struct GArgs {
    const __half* A;
    const __half* W[3];
    const float* bias[3];
    void* C[3];
    float alpha[3];
    int segw, N, K, act, out_half;
};

#define STAGES 3
#define TSTRIDE 72
#define STG_HALVES (64*TSTRIDE)
#define STG_BYTES (STG_HALVES*2)
#define GEMM_SMEM (STAGES*2*STG_BYTES)

__global__ __launch_bounds__(128, 4)
void gemm_tc_kernel(GArgs ga) {
    extern __shared__ __half smh[];
    __half* Asm = smh;                           // [STAGES][64][TSTRIDE]
    __half* Bsm = smh + (size_t)STAGES*STG_HALVES;

    int seg = blockIdx.x / ga.segw;
    int bxn = blockIdx.x % ga.segw;
    const __half* A  = ga.A;
    const __half* Wm = ga.W[seg];
    const float* bias = ga.bias[seg];
    void* Cout = ga.C[seg];
    float alpha = ga.alpha[seg];
    int N = ga.N, K = ga.K, act = ga.act, out_half = ga.out_half;

    int t = threadIdx.x;
    int lane = t & 31, warp = t >> 5;           // 4 warps
    int gid = lane >> 2, tig = lane & 3;
    int wm = (warp >> 1) * 32;                  // 0 or 32
    int wn = (warp & 1) * 32;                   // 0 or 32
    int bm = blockIdx.y * 64, bn = bxn * 64;

    float acc[2][4][4];
    #pragma unroll
    for (int i = 0; i < 2; i++)
        #pragma unroll
        for (int j = 0; j < 4; j++)
            #pragma unroll
            for (int r = 0; r < 4; r++) acc[i][j][r] = 0.f;

    // loader: thread t -> row t>>1 (0..63), 32-half (64 B) slice (t&1); 4x cp16 each
    int lrow = t >> 1;
    int lko  = (t & 1) * 32;
    const __half* Ag = A  + (size_t)(bm + lrow)*K + lko;
    const __half* Bg = Wm + (size_t)(bn + lrow)*K + lko;
    uint32_t smA0 = (uint32_t)__cvta_generic_to_shared(Asm);
    uint32_t smB0 = (uint32_t)__cvta_generic_to_shared(Bsm);
    uint32_t loff = (uint32_t)(lrow*TSTRIDE + lko) * 2;

    int KT = K >> 6;
    #pragma unroll
    for (int s = 0; s < 2; s++) {
        uint32_t sa = smA0 + (uint32_t)s*STG_BYTES + loff;
        uint32_t sb = smB0 + (uint32_t)s*STG_BYTES + loff;
        const __half* ag = Ag + s*64;
        const __half* bg = Bg + s*64;
        cp16(sa,      ag);      cp16(sa + 16, ag + 8);
        cp16(sa + 32, ag + 16); cp16(sa + 48, ag + 24);
        cp16(sb,      bg);      cp16(sb + 16, bg + 8);
        cp16(sb + 32, bg + 16); cp16(sb + 48, bg + 24);
        CP_COMMIT();
    }

    for (int kt = 0; kt < KT; kt++) {
        CP_WAIT1();
        __syncthreads();
        int nk = kt + 2;
        if (nk < KT) {
            int slot = nk % STAGES;
            uint32_t sa = smA0 + (uint32_t)slot*STG_BYTES + loff;
            uint32_t sb = smB0 + (uint32_t)slot*STG_BYTES + loff;
            const __half* ag = Ag + nk*64;
            const __half* bg = Bg + nk*64;
            cp16(sa,      ag);      cp16(sa + 16, ag + 8);
            cp16(sa + 32, ag + 16); cp16(sa + 48, ag + 24);
            cp16(sb,      bg);      cp16(sb + 16, bg + 8);
            cp16(sb + 32, bg + 16); cp16(sb + 48, bg + 24);
        }
        CP_COMMIT();

        int slot = kt % STAGES;
        const __half* Ac = Asm + (size_t)slot*STG_HALVES;
        const __half* Bb = Bsm + (size_t)slot*STG_HALVES;
        #pragma unroll
        for (int ks = 0; ks < 4; ks++) {
            int kk = ks*16 + 2*tig;
            uint32_t af[2][4], bf[4][2];
            #pragma unroll
            for (int mi = 0; mi < 2; mi++) {
                int m = wm + mi*16 + gid;
                af[mi][0] = *(const uint32_t*)&Ac[(size_t)m*TSTRIDE + kk];
                af[mi][1] = *(const uint32_t*)&Ac[(size_t)(m+8)*TSTRIDE + kk];
                af[mi][2] = *(const uint32_t*)&Ac[(size_t)m*TSTRIDE + kk + 8];
                af[mi][3] = *(const uint32_t*)&Ac[(size_t)(m+8)*TSTRIDE + kk + 8];
            }
            #pragma unroll
            for (int ni = 0; ni < 4; ni++) {
                int n = wn + ni*8 + gid;
                bf[ni][0] = *(const uint32_t*)&Bb[(size_t)n*TSTRIDE + kk];
                bf[ni][1] = *(const uint32_t*)&Bb[(size_t)n*TSTRIDE + kk + 8];
            }
            #pragma unroll
            for (int mi = 0; mi < 2; mi++)
                #pragma unroll
                for (int ni = 0; ni < 4; ni++)
                    mma_f16(acc[mi][ni], af[mi][0], af[mi][1], af[mi][2], af[mi][3],
                            bf[ni][0], bf[ni][1]);
        }
    }

    #pragma unroll
    for (int mi = 0; mi < 2; mi++) {
        #pragma unroll
        for (int ni = 0; ni < 4; ni++) {
            int col = bn + wn + ni*8 + 2*tig;
            float b0v = bias[col], b1v = bias[col+1];
            #pragma unroll
            for (int half = 0; half < 2; half++) {
                int row = bm + wm + mi*16 + gid + half*8;
                float v0 = alpha * (acc[mi][ni][half*2+0] + b0v);
                float v1 = alpha * (acc[mi][ni][half*2+1] + b1v);
                if (act) { v0 = gelu_exact(v0); v1 = gelu_exact(v1); }
                if (out_half) {
                    *(__half2*)((__half*)Cout + (size_t)row*N + col) =
                        __floats2half2_rn(v0, v1);
                } else {
                    float2 o; o.x = v0; o.y = v1;
                    *(float2*)((float*)Cout + (size_t)row*N + col) = o;
                }
            }
        }
    }
}

// ---------------- fused sliding-window attention (flash-style, fp16 mma) ----------
#define QS_OFF 0
#define PS_OFF (128*72)
#define KS_OFF (2*128*72)
#define VT_OFF (2*128*72 + 64*72)
#define ATT_SMEM ((2*128*72 + 2*64*72)*2 + 512)
__global__ __launch_bounds__(256, 2)
void fused_attn_kernel(const __half* __restrict__ q, const __half* __restrict__ k,
                       const __half* __restrict__ v, const int* __restrict__ mask,
                       __half* __restrict__ ctxh) {
    extern __shared__ __half smh[];
    __half* Qs = smh + QS_OFF;
    __half* Ps = smh + PS_OFF;
    __half* Ks = smh + KS_OFF;
    __half* Vt = smh + VT_OFF;
    float* kval = (float*)(smh + 2*128*72 + 2*64*72);
    float* v0s  = kval + 64;

    int half = blockIdx.x, n = blockIdx.y;
    int bh = blockIdx.z; int hh = bh % Hc; int b = bh / Hc;
    int s_base = n*Cc + half*128;
    int jg0 = s_base - 256;

    int t = threadIdx.x, lane = t & 31, w = t >> 5;
    int gid = lane >> 2, tig = lane & 3;
    int wm = w * 16;

    // load Q tile (128 x 64 halves)
    {
        int c8 = (t & 7) * 8;
        #pragma unroll
        for (int r = 0; r < 4; r++) {
            int row = r*32 + (t >> 3);
            uint4 qv = *(const uint4*)(q + ((size_t)(b*Sc + s_base + row))*Dc + hh*64 + c8);
            *(uint4*)&Qs[row*72 + c8] = qv;
        }
    }
    if (t < 64) v0s[t] = __half2float(v[(size_t)(b*Sc)*Dc + hh*64 + t]);

    float m0 = -1e30f, m1 = -1e30f, l0 = 0.f, l1 = 0.f;
    float ov[8][4];
    #pragma unroll
    for (int i = 0; i < 8; i++)
        #pragma unroll
        for (int r = 0; r < 4; r++) ov[i][r] = 0.f;

    int s0 = s_base + wm + gid, s1 = s0 + 8;

    for (int ch = 0; ch < 10; ch++) {
        int jgc = jg0 + ch*64;
        if (jgc + 64 <= 1 || jgc >= Sc) continue;
        __syncthreads();
        {
            int c8 = (t & 7) * 8;
            #pragma unroll
            for (int r = 0; r < 2; r++) {
                int row = r*32 + (t >> 3);
                int jg = jgc + row;
                uint4 kv = make_uint4(0,0,0,0), vv = make_uint4(0,0,0,0);
                if (jg >= 0 && jg < Sc) {
                    kv = *(const uint4*)(k + ((size_t)(b*Sc + jg))*Dc + hh*64 + c8);
                    vv = *(const uint4*)(v + ((size_t)(b*Sc + jg))*Dc + hh*64 + c8);
                }
                *(uint4*)&Ks[row*72 + c8] = kv;
                const __half* vh = (const __half*)&vv;
                #pragma unroll
                for (int i = 0; i < 8; i++)
                    Vt[(c8 + i)*72 + row] = vh[i];
            }
            if (t < 64) {
                int jg = jgc + t;
                kval[t] = (jg >= 1 && jg < Sc && mask[(size_t)b*Sc + jg] > 0) ? 1.f : 0.f;
            }
        }
        __syncthreads();

        float sc[8][4];
        #pragma unroll
        for (int i = 0; i < 8; i++)
            #pragma unroll
            for (int r = 0; r < 4; r++) sc[i][r] = 0.f;
        #pragma unroll
        for (int ks = 0; ks < 4; ks++) {
            int kk = ks*16 + 2*tig;
            uint32_t a0 = *(const uint32_t*)&Qs[(wm + gid    )*72 + kk];
            uint32_t a1 = *(const uint32_t*)&Qs[(wm + gid + 8)*72 + kk];
            uint32_t a2 = *(const uint32_t*)&Qs[(wm + gid    )*72 + kk + 8];
            uint32_t a3 = *(const uint32_t*)&Qs[(wm + gid + 8)*72 + kk + 8];
            #pragma unroll
            for (int ni = 0; ni < 8; ni++) {
                int nn = ni*8 + gid;
                uint32_t b0 = *(const uint32_t*)&Ks[nn*72 + kk];
                uint32_t b1 = *(const uint32_t*)&Ks[nn*72 + kk + 8];
                mma_f16(sc[ni], a0, a1, a2, a3, b0, b1);
            }
        }

        float cm0 = -1e30f, cm1 = -1e30f;
        unsigned vb0 = 0, vb1 = 0;
        #pragma unroll
        for (int ni = 0; ni < 8; ni++) {
            #pragma unroll
            for (int e = 0; e < 2; e++) {
                int col = ni*8 + 2*tig + e;
                int jg = jgc + col;
                bool kv_ok = kval[col] > 0.5f;
                if (kv_ok && jg >= s0-256 && jg <= s0+256) {
                    cm0 = fmaxf(cm0, sc[ni][e]); vb0 |= 1u << (ni*2+e);
                }
                if (kv_ok && jg >= s1-256 && jg <= s1+256) {
                    cm1 = fmaxf(cm1, sc[ni][2+e]); vb1 |= 1u << (ni*2+e);
                }
            }
        }
        cm0 = fmaxf(cm0, __shfl_xor_sync(0xffffffffu, cm0, 1));
        cm0 = fmaxf(cm0, __shfl_xor_sync(0xffffffffu, cm0, 2));
        cm1 = fmaxf(cm1, __shfl_xor_sync(0xffffffffu, cm1, 1));
        cm1 = fmaxf(cm1, __shfl_xor_sync(0xffffffffu, cm1, 2));
        float nm0 = fmaxf(m0, cm0), nm1 = fmaxf(m1, cm1);
        float sc0 = expf(m0 - nm0), sc1 = expf(m1 - nm1);
        m0 = nm0; m1 = nm1;
        float rs0 = 0.f, rs1 = 0.f;
        #pragma unroll
        for (int ni = 0; ni < 8; ni++) {
            float p0e0 = (vb0 >> (ni*2+0)) & 1 ? expf(sc[ni][0] - nm0) : 0.f;
            float p0e1 = (vb0 >> (ni*2+1)) & 1 ? expf(sc[ni][1] - nm0) : 0.f;
            float p1e0 = (vb1 >> (ni*2+0)) & 1 ? expf(sc[ni][2] - nm1) : 0.f;
            float p1e1 = (vb1 >> (ni*2+1)) & 1 ? expf(sc[ni][3] - nm1) : 0.f;
            rs0 += p0e0 + p0e1; rs1 += p1e0 + p1e1;
            int col2 = ni*8 + 2*tig;
            *(__half2*)&Ps[(wm + gid    )*72 + col2] = __floats2half2_rn(p0e0, p0e1);
            *(__half2*)&Ps[(wm + gid + 8)*72 + col2] = __floats2half2_rn(p1e0, p1e1);
        }
        rs0 += __shfl_xor_sync(0xffffffffu, rs0, 1);
        rs0 += __shfl_xor_sync(0xffffffffu, rs0, 2);
        rs1 += __shfl_xor_sync(0xffffffffu, rs1, 1);
        rs1 += __shfl_xor_sync(0xffffffffu, rs1, 2);
        l0 = l0*sc0 + rs0; l1 = l1*sc1 + rs1;
        #pragma unroll
        for (int ni = 0; ni < 8; ni++) {
            ov[ni][0] *= sc0; ov[ni][1] *= sc0;
            ov[ni][2] *= sc1; ov[ni][3] *= sc1;
        }
        __syncwarp();

        #pragma unroll
        for (int ks = 0; ks < 4; ks++) {
            int kk = ks*16 + 2*tig;
            uint32_t a0 = *(const uint32_t*)&Ps[(wm + gid    )*72 + kk];
            uint32_t a1 = *(const uint32_t*)&Ps[(wm + gid + 8)*72 + kk];
            uint32_t a2 = *(const uint32_t*)&Ps[(wm + gid    )*72 + kk + 8];
            uint32_t a3 = *(const uint32_t*)&Ps[(wm + gid + 8)*72 + kk + 8];
            #pragma unroll
            for (int ni = 0; ni < 8; ni++) {
                int nn = ni*8 + gid;
                uint32_t b0 = *(const uint32_t*)&Vt[nn*72 + kk];
                uint32_t b1 = *(const uint32_t*)&Vt[nn*72 + kk + 8];
                mma_f16(ov[ni], a0, a1, a2, a3, b0, b1);
            }
        }
    }

    const __half* k0p = k + (size_t)(b*Sc)*Dc + hh*64;
    const __half* q0p = q + ((size_t)(b*Sc + s0))*Dc + hh*64;
    const __half* q1p = q + ((size_t)(b*Sc + s1))*Dc + hh*64;
    float gp0 = 0.f, gp1 = 0.f;
    #pragma unroll
    for (int i = 0; i < 16; i++) {
        int d = tig*16 + i;
        float kv = __half2float(k0p[d]);
        gp0 += __half2float(q0p[d])*kv;
        gp1 += __half2float(q1p[d])*kv;
    }
    gp0 += __shfl_xor_sync(0xffffffffu, gp0, 1);
    gp0 += __shfl_xor_sync(0xffffffffu, gp0, 2);
    gp1 += __shfl_xor_sync(0xffffffffu, gp1, 1);
    gp1 += __shfl_xor_sync(0xffffffffu, gp1, 2);
    bool gok = mask[(size_t)b*Sc] > 0;
    float mf0 = gok ? fmaxf(m0, gp0) : m0;
    float mf1 = gok ? fmaxf(m1, gp1) : m1;
    float e0c = expf(m0 - mf0), e1c = expf(m1 - mf1);
    float eg0 = gok ? expf(gp0 - mf0) : 0.f;
    float eg1 = gok ? expf(gp1 - mf1) : 0.f;
    float inv0 = 1.f / (l0*e0c + eg0);
    float inv1 = 1.f / (l1*e1c + eg1);
    #pragma unroll
    for (int ni = 0; ni < 8; ni++) {
        int colb = ni*8 + 2*tig;
        float gv0 = v0s[colb], gv1 = v0s[colb+1];
        *(__half2*)(ctxh + ((size_t)(b*Sc + s0))*Dc + hh*64 + colb) =
            __floats2half2_rn((ov[ni][0]*e0c + eg0*gv0) * inv0,
                              (ov[ni][1]*e0c + eg0*gv1) * inv0);
        *(__half2*)(ctxh + ((size_t)(b*Sc + s1))*Dc + hh*64 + colb) =
            __floats2half2_rn((ov[ni][2]*e1c + eg1*gv0) * inv1,
                              (ov[ni][3]*e1c + eg1*gv1) * inv1);
    }
}

// ---------------- full-attention row 0 (global token), fp16 K/V ----------------
__global__ void attn_row0_kernel(const void* __restrict__ qb, int q_half, long q_bs,
                                 const __half* __restrict__ k, const __half* __restrict__ v,
                                 const int* __restrict__ mask,
                                 float* __restrict__ outf, __half* __restrict__ outh,
                                 long out_bs) {
    int hh = blockIdx.x, b = blockIdx.y;
    __shared__ float sc[Sc];
    __shared__ float q0s[64];
    __shared__ float red[256];
    __shared__ float part[4][64];
    int tid = threadIdx.x;
    if (tid < 64) {
        q0s[tid] = q_half ? __half2float(((const __half*)qb)[(size_t)b*q_bs + hh*64 + tid])
                          : ((const float*)qb)[(size_t)b*q_bs + hh*64 + tid];
    }
    __syncthreads();
    float lmax = NEGF;
    for (int it = 0; it < Sc/256; it++) {
        int j = tid + 256*it;
        const __half2* kr = (const __half2*)(k + ((size_t)(b*Sc + j))*Dc + hh*64);
        float s = 0.f;
        #pragma unroll
        for (int d2 = 0; d2 < 32; d2++) {
            float2 kv = __half22float2(kr[d2]);
            s += kv.x*q0s[2*d2] + kv.y*q0s[2*d2+1];
        }
        if (mask[b*Sc + j] <= 0) s = NEGF;
        sc[j] = s;
        lmax = fmaxf(lmax, s);
    }
    red[tid] = lmax; __syncthreads();
    for (int o = 128; o > 0; o >>= 1) { if (tid < o) red[tid] = fmaxf(red[tid], red[tid+o]); __syncthreads(); }
    float M = red[0]; __syncthreads();
    float lsum = 0.f;
    for (int it = 0; it < Sc/256; it++) {
        int j = tid + 256*it;
        float e = expf(sc[j] - M);
        sc[j] = e; lsum += e;
    }
    red[tid] = lsum; __syncthreads();
    for (int o = 128; o > 0; o >>= 1) { if (tid < o) red[tid] += red[tid+o]; __syncthreads(); }
    float inv = 1.0f / red[0];
    __syncthreads();
    int d = tid & 63, p = tid >> 6;
    float accd = 0.f;
    for (int j = p; j < Sc; j += 4)
        accd += sc[j] * __half2float(v[((size_t)(b*Sc + j))*Dc + hh*64 + d]);
    part[p][d] = accd;
    __syncthreads();
    if (tid < 64) {
        float o = (part[0][tid] + part[1][tid] + part[2][tid] + part[3][tid]) * inv;
        if (outh) outh[(size_t)b*out_bs + hh*64 + tid] = __float2half(o);
        else      outf[(size_t)b*out_bs + hh*64 + tid] = o;
    }
}

// ---------------- single-row GEMM (fp32 weights) ----------------
__global__ void row_gemm_kernel(const float* __restrict__ x, long x_bs,
                                const float* __restrict__ Wm, const float* __restrict__ bias,
                                float* __restrict__ out, long out_bs,
                                int K, int N, float alpha, int act) {
    extern __shared__ float xs[];
    int b = blockIdx.y;
    for (int i = threadIdx.x; i < K; i += 256) xs[i] = x[(size_t)b*x_bs + i];
    __syncthreads();
    int n = blockIdx.x*256 + threadIdx.x;
    if (n < N) {
        float acc = 0.f;
        for (int kk = 0; kk < K; kk++) acc += xs[kk] * Wm[(size_t)kk*N + n];
        float vv = alpha * (acc + bias[n]);
        if (act) vv = gelu_exact(vv);
        out[(size_t)b*out_bs + n] = vv;
    }
}

// =======================================================================
static void launch_gemm(const __half* A,
                        const __half* W0, const float* b0, void* C0, float a0,
                        const __half* W1, const float* b1, void* C1, float a1,
                        const __half* W2, const float* b2, void* C2, float a2,
                        int nseg, int N, int K, int act, int out_half) {
    GArgs ga;
    ga.A = A;
    ga.W[0] = W0; ga.W[1] = W1; ga.W[2] = W2;
    ga.bias[0] = b0; ga.bias[1] = b1; ga.bias[2] = b2;
    ga.C[0] = C0; ga.C[1] = C1; ga.C[2] = C2;
    ga.alpha[0] = a0; ga.alpha[1] = a1; ga.alpha[2] = a2;
    ga.segw = N/64; ga.N = N; ga.K = K; ga.act = act; ga.out_half = out_half;
    dim3 grid(nseg * (N/64), (Bc*Sc)/64);
    gemm_tc_kernel<<<grid, 128, GEMM_SMEM>>>(ga);
}

extern "C" void kernel_launch(void* const* d_in, const int* in_sizes, int n_in,
                              void* d_out, int out_size) {
    const int*   ids   = (const int*)d_in[0];
    const int*   mask  = (const int*)d_in[1];
    const float* etok  = (const float*)d_in[2];
    const float* epos  = (const float*)d_in[3];
    const float* eg    = (const float*)d_in[4];
    const float* ebv   = (const float*)d_in[5];
    const float* Wq    = (const float*)d_in[6];
    const float* bq    = (const float*)d_in[7];
    const float* Wk    = (const float*)d_in[8];
    const float* bk    = (const float*)d_in[9];
    const float* Wv    = (const float*)d_in[10];
    const float* bv    = (const float*)d_in[11];
    const float* Wo    = (const float*)d_in[12];
    const float* bo    = (const float*)d_in[13];
    const float* ln1g  = (const float*)d_in[14];
    const float* ln1b  = (const float*)d_in[15];
    const float* W1    = (const float*)d_in[16];
    const float* b1    = (const float*)d_in[17];
    const float* W2    = (const float*)d_in[18];
    const float* b2    = (const float*)d_in[19];
    const float* ln2g  = (const float*)d_in[20];
    const float* ln2b  = (const float*)d_in[21];
    const float* clsW  = (const float*)d_in[22];
    const float* clsb  = (const float*)d_in[23];
    float* out = (float*)d_out;

    float *h,*att,*q0,*o0,*a0,*h0,*f0,*m0;
    __half *h16,*q16,*k16,*v16,*ctxh,*midh,*wh;
    cudaGetSymbolAddress((void**)&h,    g_h);
    cudaGetSymbolAddress((void**)&h16,  g_h16);
    cudaGetSymbolAddress((void**)&q16,  g_q16);
    cudaGetSymbolAddress((void**)&k16,  g_k16);
    cudaGetSymbolAddress((void**)&v16,  g_v16);
    cudaGetSymbolAddress((void**)&ctxh, g_ctxh);
    cudaGetSymbolAddress((void**)&att,  g_att);
    cudaGetSymbolAddress((void**)&midh, g_midh);
    cudaGetSymbolAddress((void**)&wh,   g_wh);
    cudaGetSymbolAddress((void**)&q0,   g_q0);
    cudaGetSymbolAddress((void**)&o0,   g_o0);
    cudaGetSymbolAddress((void**)&a0,   g_a0);
    cudaGetSymbolAddress((void**)&h0,   g_h0);
    cudaGetSymbolAddress((void**)&f0,   g_f0);
    cudaGetSymbolAddress((void**)&m0,   g_m0);

    cudaFuncSetAttribute(gemm_tc_kernel,
        cudaFuncAttributeMaxDynamicSharedMemorySize, GEMM_SMEM);
    cudaFuncSetAttribute(fused_attn_kernel,
        cudaFuncAttributeMaxDynamicSharedMemorySize, ATT_SMEM);

    const int M = Bc*Sc;
    const size_t DD = (size_t)Dc*Dc;
    const size_t DF = (size_t)Dc*Fc;

    __half* WqH  = wh;
    __half* WkH  = wh + DD;
    __half* WvH  = wh + 2*DD;
    __half* WoH  = wh + 3*DD;
    __half* W1H  = wh + 4*DD;
    __half* W2H  = wh + 4*DD + DF;
    __half* Wk1H = wh + 4*DD + 2*DF;
    __half* Wv1H = wh + 5*DD + 2*DF;
    transpose_w<<<dim3(Dc/32, Dc/32), 256>>>(Wq, WqH, Dc, Dc);
    transpose_w<<<dim3(Dc/32, Dc/32), 256>>>(Wk, WkH, Dc, Dc);
    transpose_w<<<dim3(Dc/32, Dc/32), 256>>>(Wv, WvH, Dc, Dc);
    transpose_w<<<dim3(Dc/32, Dc/32), 256>>>(Wo, WoH, Dc, Dc);
    transpose_w<<<dim3(Fc/32, Dc/32), 256>>>(W1, W1H, Dc, Fc);
    transpose_w<<<dim3(Dc/32, Fc/32), 256>>>(W2, W2H, Fc, Dc);
    transpose_w<<<dim3(Dc/32, Dc/32), 256>>>(Wk + DD, Wk1H, Dc, Dc);
    transpose_w<<<dim3(Dc/32, Dc/32), 256>>>(Wv + DD, Wv1H, Dc, Dc);

    // ---- embeddings + LN (fused) ----
    ln_embed_kernel<<<M, 256>>>(ids, etok, epos, eg, ebv, h, h16);

    // ---- layer 0 ----
    launch_gemm(h16, WqH, bq, q16, 0.125f, WkH, bk, k16, 1.0f, WvH, bv, v16, 1.0f,
                3, Dc, Dc, 0, 1);
    fused_attn_kernel<<<dim3(2, NBc, Bc*Hc), 256, ATT_SMEM>>>(q16, k16, v16, mask, ctxh);
    attn_row0_kernel<<<dim3(Hc, Bc), 256>>>(q16, 1, (long)Sc*Dc, k16, v16, mask,
                                            nullptr, ctxh, (long)Sc*Dc);
    launch_gemm(ctxh, WoH, bo, att, 1.0f, 0,0,0,0, 0,0,0,0, 1, Dc, Dc, 0, 0);
    ln_kernel<<<M, 256>>>(h, Dc, att, Dc, ln1g, ln1b, h, Dc, h16);
    launch_gemm(h16, W1H, b1, midh, 1.0f, 0,0,0,0, 0,0,0,0, 1, Fc, Dc, 1, 1);
    launch_gemm(midh, W2H, b2, att, 1.0f, 0,0,0,0, 0,0,0,0, 1, Dc, Fc, 0, 0);
    ln_kernel<<<M, 256>>>(h, Dc, att, Dc, ln2g, ln2b, h, Dc, h16);

    // ---- layer 1 (pruned) ----
    const float* Wq1 = Wq + DD; const float* bq1 = bq + Dc;
    const float* Wo1 = Wo + DD; const float* bo1 = bo + Dc;
    const float* W11 = W1 + DF; const float* b11 = b1 + Fc;
    const float* W21 = W2 + DF; const float* b21 = b2 + Dc;
    const float* bk1 = bk + Dc; const float* bv1 = bv + Dc;

    launch_gemm(h16, Wk1H, bk1, k16, 1.0f, Wv1H, bv1, v16, 1.0f, 0,0,0,0,
                2, Dc, Dc, 0, 1);
    row_gemm_kernel<<<dim3(Dc/256, Bc), 256, Dc*sizeof(float)>>>(
        h, (long)Sc*Dc, Wq1, bq1, q0, Dc, Dc, Dc, 0.125f, 0);
    attn_row0_kernel<<<dim3(Hc, Bc), 256>>>(q0, 0, (long)Dc, k16, v16, mask,
                                            o0, nullptr, (long)Dc);
    row_gemm_kernel<<<dim3(Dc/256, Bc), 256, Dc*sizeof(float)>>>(
        o0, (long)Dc, Wo1, bo1, a0, Dc, Dc, Dc, 1.0f, 0);
    ln_kernel<<<Bc, 256>>>(h, (long)Sc*Dc, a0, Dc, ln1g + Dc, ln1b + Dc, h0, Dc, nullptr);
    row_gemm_kernel<<<dim3(Fc/256, Bc), 256, Dc*sizeof(float)>>>(
        h0, (long)Dc, W11, b11, m0, Fc, Dc, Fc, 1.0f, 1);
    row_gemm_kernel<<<dim3(Dc/256, Bc), 256, Fc*sizeof(float)>>>(
        m0, (long)Fc, W21, b21, f0, Dc, Fc, Dc, 1.0f, 0);
    ln_kernel<<<Bc, 256>>>(h0, Dc, f0, Dc, ln2g + Dc, ln2b + Dc, h0, Dc, nullptr);
    row_gemm_kernel<<<dim3(1, Bc), 256, Dc*sizeof(float)>>>(
        h0, (long)Dc, clsW, clsb, out, 3, Dc, 3, 1.0f, 0);
}

// round 15
// speedup vs baseline: 1.1214x; 1.1214x over previous
#include <cuda_runtime.h>
#include <cuda_fp16.h>
#include <math.h>
#include <stdint.h>

#define Bc 2
#define Sc 4096
#define Dc 768
#define Hc 12
#define DHc 64
#define Lc 2
#define Fc 3072
#define Cc 256
#define NBc 16
#define NEGF (-1000000000.0f)

// ---------------- scratch (device globals; no allocation allowed) ----------------
__device__ float  g_h  [(size_t)Bc*Sc*Dc];
__device__ __half g_h16[(size_t)Bc*Sc*Dc];
__device__ __half g_q16[(size_t)Bc*Sc*Dc];
__device__ __half g_k16[(size_t)Bc*Sc*Dc];
__device__ __half g_v16[(size_t)Bc*Sc*Dc];
__device__ __half g_ctxh[(size_t)Bc*Sc*Dc];
__device__ float  g_att[(size_t)Bc*Sc*Dc];
__device__ __half g_midh[(size_t)Bc*Sc*Fc];
__device__ __half g_wh [8257536];              // transposed fp16 weights
__device__ float  g_q0 [Bc*Dc];
__device__ float  g_o0 [Bc*Dc];
__device__ float  g_a0 [Bc*Dc];
__device__ float  g_h0 [Bc*Dc];
__device__ float  g_f0 [Bc*Dc];
__device__ float  g_m0 [Bc*Fc];

__device__ __forceinline__ float gelu_exact(float x) {
    return 0.5f * x * (1.0f + erff(x * 0.70710678118654752f));
}

__device__ __forceinline__ void mma_f16(float* c,
    uint32_t a0, uint32_t a1, uint32_t a2, uint32_t a3,
    uint32_t b0, uint32_t b1) {
    asm volatile(
        "mma.sync.aligned.m16n8k16.row.col.f32.f16.f16.f32 "
        "{%0,%1,%2,%3}, {%4,%5,%6,%7}, {%8,%9}, {%0,%1,%2,%3};"
        : "+f"(c[0]), "+f"(c[1]), "+f"(c[2]), "+f"(c[3])
        : "r"(a0), "r"(a1), "r"(a2), "r"(a3), "r"(b0), "r"(b1));
}

__device__ __forceinline__ void cp16(uint32_t s, const void* g) {
    asm volatile("cp.async.cg.shared.global [%0], [%1], 16;" :: "r"(s), "l"(g));
}
#define CP_COMMIT() asm volatile("cp.async.commit_group;")
#define CP_WAIT1()  asm volatile("cp.async.wait_group 1;")

__device__ __forceinline__ float warp_sum(float x) {
    #pragma unroll
    for (int o = 16; o > 0; o >>= 1) x += __shfl_xor_sync(0xffffffffu, x, o);
    return x;
}

// ---------------- weight transpose+convert: W[K,N] fp32 -> Wh[N,K] fp16 ----------
__global__ void transpose_w(const float* __restrict__ W, __half* __restrict__ Wh,
                            int K, int N) {
    __shared__ float tile[32][33];
    int kb = blockIdx.y*32, nb = blockIdx.x*32;
    int tx = threadIdx.x & 31, ty = threadIdx.x >> 5;
    #pragma unroll
    for (int j = 0; j < 32; j += 8)
        tile[ty+j][tx] = W[(size_t)(kb+ty+j)*N + nb+tx];
    __syncthreads();
    #pragma unroll
    for (int j = 0; j < 32; j += 8)
        Wh[(size_t)(nb+ty+j)*K + kb+tx] = __float2half(tile[tx][ty+j]);
}

// ---------------- fused embedding + LayerNorm (shuffle reduction) ----------------
__global__ void ln_embed_kernel(const int* __restrict__ ids,
                                const float* __restrict__ tok, const float* __restrict__ pos,
                                const float* __restrict__ g, const float* __restrict__ bb,
                                float* __restrict__ out, __half* __restrict__ outh) {
    __shared__ float red1[8], red2[8];
    int row = blockIdx.x, t = threadIdx.x;
    int lane = t & 31, wid = t >> 5;
    int s = row % Sc;
    const float* tk = tok + (size_t)ids[row]*Dc;
    const float* pp = pos + (size_t)s*Dc;
    float v0 = tk[t]+pp[t], v1 = tk[t+256]+pp[t+256], v2 = tk[t+512]+pp[t+512];
    float sm = warp_sum(v0 + v1 + v2);
    if (lane == 0) red1[wid] = sm;
    __syncthreads();
    float tot = 0.f;
    #pragma unroll
    for (int i = 0; i < 8; i++) tot += red1[i];
    float mean = tot * (1.0f/768.0f);
    float d0 = v0-mean, d1 = v1-mean, d2 = v2-mean;
    float vs = warp_sum(d0*d0 + d1*d1 + d2*d2);
    if (lane == 0) red2[wid] = vs;
    __syncthreads();
    float vtot = 0.f;
    #pragma unroll
    for (int i = 0; i < 8; i++) vtot += red2[i];
    float rstd = rsqrtf(vtot * (1.0f/768.0f) + 1e-5f);
    float o0 = d0*rstd*g[t]     + bb[t];
    float o1 = d1*rstd*g[t+256] + bb[t+256];
    float o2 = d2*rstd*g[t+512] + bb[t+512];
    float* orow = out + (size_t)row * Dc;
    orow[t] = o0; orow[t+256] = o1; orow[t+512] = o2;
    __half* hrow = outh + (size_t)row * Dc;
    hrow[t] = __float2half(o0); hrow[t+256] = __float2half(o1); hrow[t+512] = __float2half(o2);
}

// ---------------- LayerNorm; residual; optional fp16 second output (shuffle) -----
__global__ void ln_kernel(const float* __restrict__ x, long xs,
                          const float* __restrict__ res, long rs,
                          const float* __restrict__ g, const float* __restrict__ bb,
                          float* __restrict__ out, long os, __half* __restrict__ outh) {
    __shared__ float red1[8], red2[8];
    int row = blockIdx.x, t = threadIdx.x;
    int lane = t & 31, wid = t >> 5;
    const float* xr = x + (size_t)row * xs;
    float v0 = xr[t], v1 = xr[t+256], v2 = xr[t+512];
    if (res) {
        const float* rr = res + (size_t)row * rs;
        v0 += rr[t]; v1 += rr[t+256]; v2 += rr[t+512];
    }
    float sm = warp_sum(v0 + v1 + v2);
    if (lane == 0) red1[wid] = sm;
    __syncthreads();
    float tot = 0.f;
    #pragma unroll
    for (int i = 0; i < 8; i++) tot += red1[i];
    float mean = tot * (1.0f/768.0f);
    float d0 = v0-mean, d1 = v1-mean, d2 = v2-mean;
    float vs = warp_sum(d0*d0 + d1*d1 + d2*d2);
    if (lane == 0) red2[wid] = vs;
    __syncthreads();
    float vtot = 0.f;
    #pragma unroll
    for (int i = 0; i < 8; i++) vtot += red2[i];
    float rstd = rsqrtf(vtot * (1.0f/768.0f) + 1e-5f);
    float o0 = d0*rstd*g[t]     + bb[t];
    float o1 = d1*rstd*g[t+256] + bb[t+256];
    float o2 = d2*rstd*g[t+512] + bb[t+512];
    float* orow = out + (size_t)row * os;
    orow[t] = o0; orow[t+256] = o1; orow[t+512] = o2;
    if (outh) {
        __half* hrow = outh + (size_t)row * os;
        hrow[t] = __float2half(o0); hrow[t+256] = __float2half(o1); hrow[t+512] = __float2half(o2);
    }
}

// ---------------- fp16 GEMM, 128x128 tile, K-tile 64, 3-stage cp.async (R10) -----
struct GArgs {
    const __half* A;
    const __half* W[3];
    const float* bias[3];
    void* C[3];
    float alpha[3];
    int segw, N, K, act, out_half;
};

#define STAGES 3
#define TSTRIDE 72
#define STG_HALVES (128*TSTRIDE)
#define STG_BYTES (STG_HALVES*2)
#define GEMM_SMEM (STAGES*2*STG_BYTES)

__global__ __launch_bounds__(256, 2)
void gemm_tc_kernel(GArgs ga) {
    extern __shared__ __half smh[];
    __half* Asm = smh;
    __half* Bsm = smh + (size_t)STAGES*STG_HALVES;

    int seg = blockIdx.x / ga.segw;
    int bxn = blockIdx.x % ga.segw;
    const __half* A  = ga.A;
    const __half* Wm = ga.W[seg];
    const float* bias = ga.bias[seg];
    void* Cout = ga.C[seg];
    float alpha = ga.alpha[seg];
    int N = ga.N, K = ga.K, act = ga.act, out_half = ga.out_half;

    int t = threadIdx.x;
    int lane = t & 31, warp = t >> 5;
    int gid = lane >> 2, tig = lane & 3;
    int wm = (warp >> 2) * 64;
    int wn = (warp & 3) * 32;
    int bm = blockIdx.y * 128, bn = bxn * 128;

    float acc[4][4][4];
    #pragma unroll
    for (int i = 0; i < 4; i++)
        #pragma unroll
        for (int j = 0; j < 4; j++)
            #pragma unroll
            for (int r = 0; r < 4; r++) acc[i][j][r] = 0.f;

    int lrow = t >> 1;
    int lko  = (t & 1) * 32;
    const __half* Ag = A  + (size_t)(bm + lrow)*K + lko;
    const __half* Bg = Wm + (size_t)(bn + lrow)*K + lko;
    uint32_t smA0 = (uint32_t)__cvta_generic_to_shared(Asm);
    uint32_t smB0 = (uint32_t)__cvta_generic_to_shared(Bsm);
    uint32_t loff = (uint32_t)(lrow*TSTRIDE + lko) * 2;

    int KT = K >> 6;
    #pragma unroll
    for (int s = 0; s < 2; s++) {
        uint32_t sa = smA0 + (uint32_t)s*STG_BYTES + loff;
        uint32_t sb = smB0 + (uint32_t)s*STG_BYTES + loff;
        const __half* ag = Ag + s*64;
        const __half* bg = Bg + s*64;
        cp16(sa,      ag);      cp16(sa + 16, ag + 8);
        cp16(sa + 32, ag + 16); cp16(sa + 48, ag + 24);
        cp16(sb,      bg);      cp16(sb + 16, bg + 8);
        cp16(sb + 32, bg + 16); cp16(sb + 48, bg + 24);
        CP_COMMIT();
    }

    for (int kt = 0; kt < KT; kt++) {
        CP_WAIT1();
        __syncthreads();
        int nk = kt + 2;
        if (nk < KT) {
            int slot = nk % STAGES;
            uint32_t sa = smA0 + (uint32_t)slot*STG_BYTES + loff;
            uint32_t sb = smB0 + (uint32_t)slot*STG_BYTES + loff;
            const __half* ag = Ag + nk*64;
            const __half* bg = Bg + nk*64;
            cp16(sa,      ag);      cp16(sa + 16, ag + 8);
            cp16(sa + 32, ag + 16); cp16(sa + 48, ag + 24);
            cp16(sb,      bg);      cp16(sb + 16, bg + 8);
            cp16(sb + 32, bg + 16); cp16(sb + 48, bg + 24);
        }
        CP_COMMIT();

        int slot = kt % STAGES;
        const __half* Ac = Asm + (size_t)slot*STG_HALVES;
        const __half* Bb = Bsm + (size_t)slot*STG_HALVES;
        #pragma unroll
        for (int ks = 0; ks < 4; ks++) {
            int kk = ks*16 + 2*tig;
            uint32_t af[4][4], bf[4][2];
            #pragma unroll
            for (int mi = 0; mi < 4; mi++) {
                int m = wm + mi*16 + gid;
                af[mi][0] = *(const uint32_t*)&Ac[(size_t)m*TSTRIDE + kk];
                af[mi][1] = *(const uint32_t*)&Ac[(size_t)(m+8)*TSTRIDE + kk];
                af[mi][2] = *(const uint32_t*)&Ac[(size_t)m*TSTRIDE + kk + 8];
                af[mi][3] = *(const uint32_t*)&Ac[(size_t)(m+8)*TSTRIDE + kk + 8];
            }
            #pragma unroll
            for (int ni = 0; ni < 4; ni++) {
                int n = wn + ni*8 + gid;
                bf[ni][0] = *(const uint32_t*)&Bb[(size_t)n*TSTRIDE + kk];
                bf[ni][1] = *(const uint32_t*)&Bb[(size_t)n*TSTRIDE + kk + 8];
            }
            #pragma unroll
            for (int mi = 0; mi < 4; mi++)
                #pragma unroll
                for (int ni = 0; ni < 4; ni++)
                    mma_f16(acc[mi][ni], af[mi][0], af[mi][1], af[mi][2], af[mi][3],
                            bf[ni][0], bf[ni][1]);
        }
    }

    #pragma unroll
    for (int mi = 0; mi < 4; mi++) {
        #pragma unroll
        for (int ni = 0; ni < 4; ni++) {
            int col = bn + wn + ni*8 + 2*tig;
            float b0v = bias[col], b1v = bias[col+1];
            #pragma unroll
            for (int half = 0; half < 2; half++) {
                int row = bm + wm + mi*16 + gid + half*8;
                float v0 = alpha * (acc[mi][ni][half*2+0] + b0v);
                float v1 = alpha * (acc[mi][ni][half*2+1] + b1v);
                if (act) { v0 = gelu_exact(v0); v1 = gelu_exact(v1); }
                if (out_half) {
                    *(__half2*)((__half*)Cout + (size_t)row*N + col) =
                        __floats2half2_rn(v0, v1);
                } else {
                    float2 o; o.x = v0; o.y = v1;
                    *(float2*)((float*)Cout + (size_t)row*N + col) = o;
                }
            }
        }
    }
}

// ---------------- fused sliding-window attention (flash-style, fp16 mma) ----------
#define QS_OFF 0
#define PS_OFF (128*72)
#define KS_OFF (2*128*72)
#define VT_OFF (2*128*72 + 64*72)
#define ATT_SMEM ((2*128*72 + 2*64*72)*2 + 512)
__global__ __launch_bounds__(256, 2)
void fused_attn_kernel(const __half* __restrict__ q, const __half* __restrict__ k,
                       const __half* __restrict__ v, const int* __restrict__ mask,
                       __half* __restrict__ ctxh) {
    extern __shared__ __half smh[];
    __half* Qs = smh + QS_OFF;
    __half* Ps = smh + PS_OFF;
    __half* Ks = smh + KS_OFF;
    __half* Vt = smh + VT_OFF;
    float* kval = (float*)(smh + 2*128*72 + 2*64*72);
    float* v0s  = kval + 64;

    int half = blockIdx.x, n = blockIdx.y;
    int bh = blockIdx.z; int hh = bh % Hc; int b = bh / Hc;
    int s_base = n*Cc + half*128;
    int jg0 = s_base - 256;

    int t = threadIdx.x, lane = t & 31, w = t >> 5;
    int gid = lane >> 2, tig = lane & 3;
    int wm = w * 16;

    {
        int c8 = (t & 7) * 8;
        #pragma unroll
        for (int r = 0; r < 4; r++) {
            int row = r*32 + (t >> 3);
            uint4 qv = *(const uint4*)(q + ((size_t)(b*Sc + s_base + row))*Dc + hh*64 + c8);
            *(uint4*)&Qs[row*72 + c8] = qv;
        }
    }
    if (t < 64) v0s[t] = __half2float(v[(size_t)(b*Sc)*Dc + hh*64 + t]);

    float m0 = -1e30f, m1 = -1e30f, l0 = 0.f, l1 = 0.f;
    float ov[8][4];
    #pragma unroll
    for (int i = 0; i < 8; i++)
        #pragma unroll
        for (int r = 0; r < 4; r++) ov[i][r] = 0.f;

    int s0 = s_base + wm + gid, s1 = s0 + 8;

    for (int ch = 0; ch < 10; ch++) {
        int jgc = jg0 + ch*64;
        if (jgc + 64 <= 1 || jgc >= Sc) continue;
        __syncthreads();
        {
            int c8 = (t & 7) * 8;
            #pragma unroll
            for (int r = 0; r < 2; r++) {
                int row = r*32 + (t >> 3);
                int jg = jgc + row;
                uint4 kv = make_uint4(0,0,0,0), vv = make_uint4(0,0,0,0);
                if (jg >= 0 && jg < Sc) {
                    kv = *(const uint4*)(k + ((size_t)(b*Sc + jg))*Dc + hh*64 + c8);
                    vv = *(const uint4*)(v + ((size_t)(b*Sc + jg))*Dc + hh*64 + c8);
                }
                *(uint4*)&Ks[row*72 + c8] = kv;
                const __half* vh = (const __half*)&vv;
                #pragma unroll
                for (int i = 0; i < 8; i++)
                    Vt[(c8 + i)*72 + row] = vh[i];
            }
            if (t < 64) {
                int jg = jgc + t;
                kval[t] = (jg >= 1 && jg < Sc && mask[(size_t)b*Sc + jg] > 0) ? 1.f : 0.f;
            }
        }
        __syncthreads();

        float sc[8][4];
        #pragma unroll
        for (int i = 0; i < 8; i++)
            #pragma unroll
            for (int r = 0; r < 4; r++) sc[i][r] = 0.f;
        #pragma unroll
        for (int ks = 0; ks < 4; ks++) {
            int kk = ks*16 + 2*tig;
            uint32_t a0 = *(const uint32_t*)&Qs[(wm + gid    )*72 + kk];
            uint32_t a1 = *(const uint32_t*)&Qs[(wm + gid + 8)*72 + kk];
            uint32_t a2 = *(const uint32_t*)&Qs[(wm + gid    )*72 + kk + 8];
            uint32_t a3 = *(const uint32_t*)&Qs[(wm + gid + 8)*72 + kk + 8];
            #pragma unroll
            for (int ni = 0; ni < 8; ni++) {
                int nn = ni*8 + gid;
                uint32_t b0 = *(const uint32_t*)&Ks[nn*72 + kk];
                uint32_t b1 = *(const uint32_t*)&Ks[nn*72 + kk + 8];
                mma_f16(sc[ni], a0, a1, a2, a3, b0, b1);
            }
        }

        float cm0 = -1e30f, cm1 = -1e30f;
        unsigned vb0 = 0, vb1 = 0;
        #pragma unroll
        for (int ni = 0; ni < 8; ni++) {
            #pragma unroll
            for (int e = 0; e < 2; e++) {
                int col = ni*8 + 2*tig + e;
                int jg = jgc + col;
                bool kv_ok = kval[col] > 0.5f;
                if (kv_ok && jg >= s0-256 && jg <= s0+256) {
                    cm0 = fmaxf(cm0, sc[ni][e]); vb0 |= 1u << (ni*2+e);
                }
                if (kv_ok && jg >= s1-256 && jg <= s1+256) {
                    cm1 = fmaxf(cm1, sc[ni][2+e]); vb1 |= 1u << (ni*2+e);
                }
            }
        }
        cm0 = fmaxf(cm0, __shfl_xor_sync(0xffffffffu, cm0, 1));
        cm0 = fmaxf(cm0, __shfl_xor_sync(0xffffffffu, cm0, 2));
        cm1 = fmaxf(cm1, __shfl_xor_sync(0xffffffffu, cm1, 1));
        cm1 = fmaxf(cm1, __shfl_xor_sync(0xffffffffu, cm1, 2));
        float nm0 = fmaxf(m0, cm0), nm1 = fmaxf(m1, cm1);
        float sc0 = expf(m0 - nm0), sc1 = expf(m1 - nm1);
        m0 = nm0; m1 = nm1;
        float rs0 = 0.f, rs1 = 0.f;
        #pragma unroll
        for (int ni = 0; ni < 8; ni++) {
            float p0e0 = (vb0 >> (ni*2+0)) & 1 ? expf(sc[ni][0] - nm0) : 0.f;
            float p0e1 = (vb0 >> (ni*2+1)) & 1 ? expf(sc[ni][1] - nm0) : 0.f;
            float p1e0 = (vb1 >> (ni*2+0)) & 1 ? expf(sc[ni][2] - nm1) : 0.f;
            float p1e1 = (vb1 >> (ni*2+1)) & 1 ? expf(sc[ni][3] - nm1) : 0.f;
            rs0 += p0e0 + p0e1; rs1 += p1e0 + p1e1;
            int col2 = ni*8 + 2*tig;
            *(__half2*)&Ps[(wm + gid    )*72 + col2] = __floats2half2_rn(p0e0, p0e1);
            *(__half2*)&Ps[(wm + gid + 8)*72 + col2] = __floats2half2_rn(p1e0, p1e1);
        }
        rs0 += __shfl_xor_sync(0xffffffffu, rs0, 1);
        rs0 += __shfl_xor_sync(0xffffffffu, rs0, 2);
        rs1 += __shfl_xor_sync(0xffffffffu, rs1, 1);
        rs1 += __shfl_xor_sync(0xffffffffu, rs1, 2);
        l0 = l0*sc0 + rs0; l1 = l1*sc1 + rs1;
        #pragma unroll
        for (int ni = 0; ni < 8; ni++) {
            ov[ni][0] *= sc0; ov[ni][1] *= sc0;
            ov[ni][2] *= sc1; ov[ni][3] *= sc1;
        }
        __syncwarp();

        #pragma unroll
        for (int ks = 0; ks < 4; ks++) {
            int kk = ks*16 + 2*tig;
            uint32_t a0 = *(const uint32_t*)&Ps[(wm + gid    )*72 + kk];
            uint32_t a1 = *(const uint32_t*)&Ps[(wm + gid + 8)*72 + kk];
            uint32_t a2 = *(const uint32_t*)&Ps[(wm + gid    )*72 + kk + 8];
            uint32_t a3 = *(const uint32_t*)&Ps[(wm + gid + 8)*72 + kk + 8];
            #pragma unroll
            for (int ni = 0; ni < 8; ni++) {
                int nn = ni*8 + gid;
                uint32_t b0 = *(const uint32_t*)&Vt[nn*72 + kk];
                uint32_t b1 = *(const uint32_t*)&Vt[nn*72 + kk + 8];
                mma_f16(ov[ni], a0, a1, a2, a3, b0, b1);
            }
        }
    }

    const __half* k0p = k + (size_t)(b*Sc)*Dc + hh*64;
    const __half* q0p = q + ((size_t)(b*Sc + s0))*Dc + hh*64;
    const __half* q1p = q + ((size_t)(b*Sc + s1))*Dc + hh*64;
    float gp0 = 0.f, gp1 = 0.f;
    #pragma unroll
    for (int i = 0; i < 16; i++) {
        int d = tig*16 + i;
        float kv = __half2float(k0p[d]);
        gp0 += __half2float(q0p[d])*kv;
        gp1 += __half2float(q1p[d])*kv;
    }
    gp0 += __shfl_xor_sync(0xffffffffu, gp0, 1);
    gp0 += __shfl_xor_sync(0xffffffffu, gp0, 2);
    gp1 += __shfl_xor_sync(0xffffffffu, gp1, 1);
    gp1 += __shfl_xor_sync(0xffffffffu, gp1, 2);
    bool gok = mask[(size_t)b*Sc] > 0;
    float mf0 = gok ? fmaxf(m0, gp0) : m0;
    float mf1 = gok ? fmaxf(m1, gp1) : m1;
    float e0c = expf(m0 - mf0), e1c = expf(m1 - mf1);
    float eg0 = gok ? expf(gp0 - mf0) : 0.f;
    float eg1 = gok ? expf(gp1 - mf1) : 0.f;
    float inv0 = 1.f / (l0*e0c + eg0);
    float inv1 = 1.f / (l1*e1c + eg1);
    #pragma unroll
    for (int ni = 0; ni < 8; ni++) {
        int colb = ni*8 + 2*tig;
        float gv0 = v0s[colb], gv1 = v0s[colb+1];
        *(__half2*)(ctxh + ((size_t)(b*Sc + s0))*Dc + hh*64 + colb) =
            __floats2half2_rn((ov[ni][0]*e0c + eg0*gv0) * inv0,
                              (ov[ni][1]*e0c + eg0*gv1) * inv0);
        *(__half2*)(ctxh + ((size_t)(b*Sc + s1))*Dc + hh*64 + colb) =
            __floats2half2_rn((ov[ni][2]*e1c + eg1*gv0) * inv1,
                              (ov[ni][3]*e1c + eg1*gv1) * inv1);
    }
}

// ---------------- full-attention row 0 (global token), fp16 K/V ----------------
__global__ void attn_row0_kernel(const void* __restrict__ qb, int q_half, long q_bs,
                                 const __half* __restrict__ k, const __half* __restrict__ v,
                                 const int* __restrict__ mask,
                                 float* __restrict__ outf, __half* __restrict__ outh,
                                 long out_bs) {
    int hh = blockIdx.x, b = blockIdx.y;
    __shared__ float sc[Sc];
    __shared__ float q0s[64];
    __shared__ float red[256];
    __shared__ float part[4][64];
    int tid = threadIdx.x;
    if (tid < 64) {
        q0s[tid] = q_half ? __half2float(((const __half*)qb)[(size_t)b*q_bs + hh*64 + tid])
                          : ((const float*)qb)[(size_t)b*q_bs + hh*64 + tid];
    }
    __syncthreads();
    float lmax = NEGF;
    for (int it = 0; it < Sc/256; it++) {
        int j = tid + 256*it;
        const __half2* kr = (const __half2*)(k + ((size_t)(b*Sc + j))*Dc + hh*64);
        float s = 0.f;
        #pragma unroll
        for (int d2 = 0; d2 < 32; d2++) {
            float2 kv = __half22float2(kr[d2]);
            s += kv.x*q0s[2*d2] + kv.y*q0s[2*d2+1];
        }
        if (mask[b*Sc + j] <= 0) s = NEGF;
        sc[j] = s;
        lmax = fmaxf(lmax, s);
    }
    red[tid] = lmax; __syncthreads();
    for (int o = 128; o > 0; o >>= 1) { if (tid < o) red[tid] = fmaxf(red[tid], red[tid+o]); __syncthreads(); }
    float M = red[0]; __syncthreads();
    float lsum = 0.f;
    for (int it = 0; it < Sc/256; it++) {
        int j = tid + 256*it;
        float e = expf(sc[j] - M);
        sc[j] = e; lsum += e;
    }
    red[tid] = lsum; __syncthreads();
    for (int o = 128; o > 0; o >>= 1) { if (tid < o) red[tid] += red[tid+o]; __syncthreads(); }
    float inv = 1.0f / red[0];
    __syncthreads();
    int d = tid & 63, p = tid >> 6;
    float accd = 0.f;
    for (int j = p; j < Sc; j += 4)
        accd += sc[j] * __half2float(v[((size_t)(b*Sc + j))*Dc + hh*64 + d]);
    part[p][d] = accd;
    __syncthreads();
    if (tid < 64) {
        float o = (part[0][tid] + part[1][tid] + part[2][tid] + part[3][tid]) * inv;
        if (outh) outh[(size_t)b*out_bs + hh*64 + tid] = __float2half(o);
        else      outf[(size_t)b*out_bs + hh*64 + tid] = o;
    }
}

// ---------------- single-row GEMM (fp32 weights) ----------------
__global__ void row_gemm_kernel(const float* __restrict__ x, long x_bs,
                                const float* __restrict__ Wm, const float* __restrict__ bias,
                                float* __restrict__ out, long out_bs,
                                int K, int N, float alpha, int act) {
    extern __shared__ float xs[];
    int b = blockIdx.y;
    for (int i = threadIdx.x; i < K; i += 256) xs[i] = x[(size_t)b*x_bs + i];
    __syncthreads();
    int n = blockIdx.x*256 + threadIdx.x;
    if (n < N) {
        float acc = 0.f;
        for (int kk = 0; kk < K; kk++) acc += xs[kk] * Wm[(size_t)kk*N + n];
        float vv = alpha * (acc + bias[n]);
        if (act) vv = gelu_exact(vv);
        out[(size_t)b*out_bs + n] = vv;
    }
}

// =======================================================================
static void launch_gemm(const __half* A,
                        const __half* W0, const float* b0, void* C0, float a0,
                        const __half* W1, const float* b1, void* C1, float a1,
                        const __half* W2, const float* b2, void* C2, float a2,
                        int nseg, int N, int K, int act, int out_half) {
    GArgs ga;
    ga.A = A;
    ga.W[0] = W0; ga.W[1] = W1; ga.W[2] = W2;
    ga.bias[0] = b0; ga.bias[1] = b1; ga.bias[2] = b2;
    ga.C[0] = C0; ga.C[1] = C1; ga.C[2] = C2;
    ga.alpha[0] = a0; ga.alpha[1] = a1; ga.alpha[2] = a2;
    ga.segw = N/128; ga.N = N; ga.K = K; ga.act = act; ga.out_half = out_half;
    dim3 grid(nseg * (N/128), (Bc*Sc)/128);
    gemm_tc_kernel<<<grid, 256, GEMM_SMEM>>>(ga);
}

extern "C" void kernel_launch(void* const* d_in, const int* in_sizes, int n_in,
                              void* d_out, int out_size) {
    const int*   ids   = (const int*)d_in[0];
    const int*   mask  = (const int*)d_in[1];
    const float* etok  = (const float*)d_in[2];
    const float* epos  = (const float*)d_in[3];
    const float* eg    = (const float*)d_in[4];
    const float* ebv   = (const float*)d_in[5];
    const float* Wq    = (const float*)d_in[6];
    const float* bq    = (const float*)d_in[7];
    const float* Wk    = (const float*)d_in[8];
    const float* bk    = (const float*)d_in[9];
    const float* Wv    = (const float*)d_in[10];
    const float* bv    = (const float*)d_in[11];
    const float* Wo    = (const float*)d_in[12];
    const float* bo    = (const float*)d_in[13];
    const float* ln1g  = (const float*)d_in[14];
    const float* ln1b  = (const float*)d_in[15];
    const float* W1    = (const float*)d_in[16];
    const float* b1    = (const float*)d_in[17];
    const float* W2    = (const float*)d_in[18];
    const float* b2    = (const float*)d_in[19];
    const float* ln2g  = (const float*)d_in[20];
    const float* ln2b  = (const float*)d_in[21];
    const float* clsW  = (const float*)d_in[22];
    const float* clsb  = (const float*)d_in[23];
    float* out = (float*)d_out;

    float *h,*att,*q0,*o0,*a0,*h0,*f0,*m0;
    __half *h16,*q16,*k16,*v16,*ctxh,*midh,*wh;
    cudaGetSymbolAddress((void**)&h,    g_h);
    cudaGetSymbolAddress((void**)&h16,  g_h16);
    cudaGetSymbolAddress((void**)&q16,  g_q16);
    cudaGetSymbolAddress((void**)&k16,  g_k16);
    cudaGetSymbolAddress((void**)&v16,  g_v16);
    cudaGetSymbolAddress((void**)&ctxh, g_ctxh);
    cudaGetSymbolAddress((void**)&att,  g_att);
    cudaGetSymbolAddress((void**)&midh, g_midh);
    cudaGetSymbolAddress((void**)&wh,   g_wh);
    cudaGetSymbolAddress((void**)&q0,   g_q0);
    cudaGetSymbolAddress((void**)&o0,   g_o0);
    cudaGetSymbolAddress((void**)&a0,   g_a0);
    cudaGetSymbolAddress((void**)&h0,   g_h0);
    cudaGetSymbolAddress((void**)&f0,   g_f0);
    cudaGetSymbolAddress((void**)&m0,   g_m0);

    cudaFuncSetAttribute(gemm_tc_kernel,
        cudaFuncAttributeMaxDynamicSharedMemorySize, GEMM_SMEM);
    cudaFuncSetAttribute(fused_attn_kernel,
        cudaFuncAttributeMaxDynamicSharedMemorySize, ATT_SMEM);

    const int M = Bc*Sc;
    const size_t DD = (size_t)Dc*Dc;
    const size_t DF = (size_t)Dc*Fc;

    __half* WqH  = wh;
    __half* WkH  = wh + DD;
    __half* WvH  = wh + 2*DD;
    __half* WoH  = wh + 3*DD;
    __half* W1H  = wh + 4*DD;
    __half* W2H  = wh + 4*DD + DF;
    __half* Wk1H = wh + 4*DD + 2*DF;
    __half* Wv1H = wh + 5*DD + 2*DF;
    transpose_w<<<dim3(Dc/32, Dc/32), 256>>>(Wq, WqH, Dc, Dc);
    transpose_w<<<dim3(Dc/32, Dc/32), 256>>>(Wk, WkH, Dc, Dc);
    transpose_w<<<dim3(Dc/32, Dc/32), 256>>>(Wv, WvH, Dc, Dc);
    transpose_w<<<dim3(Dc/32, Dc/32), 256>>>(Wo, WoH, Dc, Dc);
    transpose_w<<<dim3(Fc/32, Dc/32), 256>>>(W1, W1H, Dc, Fc);
    transpose_w<<<dim3(Dc/32, Fc/32), 256>>>(W2, W2H, Fc, Dc);
    transpose_w<<<dim3(Dc/32, Dc/32), 256>>>(Wk + DD, Wk1H, Dc, Dc);
    transpose_w<<<dim3(Dc/32, Dc/32), 256>>>(Wv + DD, Wv1H, Dc, Dc);

    // ---- embeddings + LN (fused) ----
    ln_embed_kernel<<<M, 256>>>(ids, etok, epos, eg, ebv, h, h16);

    // ---- layer 0 ----
    launch_gemm(h16, WqH, bq, q16, 0.125f, WkH, bk, k16, 1.0f, WvH, bv, v16, 1.0f,
                3, Dc, Dc, 0, 1);
    fused_attn_kernel<<<dim3(2, NBc, Bc*Hc), 256, ATT_SMEM>>>(q16, k16, v16, mask, ctxh);
    attn_row0_kernel<<<dim3(Hc, Bc), 256>>>(q16, 1, (long)Sc*Dc, k16, v16, mask,
                                            nullptr, ctxh, (long)Sc*Dc);
    launch_gemm(ctxh, WoH, bo, att, 1.0f, 0,0,0,0, 0,0,0,0, 1, Dc, Dc, 0, 0);
    ln_kernel<<<M, 256>>>(h, Dc, att, Dc, ln1g, ln1b, h, Dc, h16);
    launch_gemm(h16, W1H, b1, midh, 1.0f, 0,0,0,0, 0,0,0,0, 1, Fc, Dc, 1, 1);
    launch_gemm(midh, W2H, b2, att, 1.0f, 0,0,0,0, 0,0,0,0, 1, Dc, Fc, 0, 0);
    ln_kernel<<<M, 256>>>(h, Dc, att, Dc, ln2g, ln2b, h, Dc, h16);

    // ---- layer 1 (pruned) ----
    const float* Wq1 = Wq + DD; const float* bq1 = bq + Dc;
    const float* Wo1 = Wo + DD; const float* bo1 = bo + Dc;
    const float* W11 = W1 + DF; const float* b11 = b1 + Fc;
    const float* W21 = W2 + DF; const float* b21 = b2 + Dc;
    const float* bk1 = bk + Dc; const float* bv1 = bv + Dc;

    launch_gemm(h16, Wk1H, bk1, k16, 1.0f, Wv1H, bv1, v16, 1.0f, 0,0,0,0,
                2, Dc, Dc, 0, 1);
    row_gemm_kernel<<<dim3(Dc/256, Bc), 256, Dc*sizeof(float)>>>(
        h, (long)Sc*Dc, Wq1, bq1, q0, Dc, Dc, Dc, 0.125f, 0);
    attn_row0_kernel<<<dim3(Hc, Bc), 256>>>(q0, 0, (long)Dc, k16, v16, mask,
                                            o0, nullptr, (long)Dc);
    row_gemm_kernel<<<dim3(Dc/256, Bc), 256, Dc*sizeof(float)>>>(
        o0, (long)Dc, Wo1, bo1, a0, Dc, Dc, Dc, 1.0f, 0);
    ln_kernel<<<Bc, 256>>>(h, (long)Sc*Dc, a0, Dc, ln1g + Dc, ln1b + Dc, h0, Dc, nullptr);
    row_gemm_kernel<<<dim3(Fc/256, Bc), 256, Dc*sizeof(float)>>>(
        h0, (long)Dc, W11, b11, m0, Fc, Dc, Fc, 1.0f, 1);
    row_gemm_kernel<<<dim3(Dc/256, Bc), 256, Fc*sizeof(float)>>>(
        m0, (long)Fc, W21, b21, f0, Dc, Fc, Dc, 1.0f, 0);
    ln_kernel<<<Bc, 256>>>(h0, Dc, f0, Dc, ln2g + Dc, ln2b + Dc, h0, Dc, nullptr);
    row_gemm_kernel<<<dim3(1, Bc), 256, Dc*sizeof(float)>>>(
        h0, (long)Dc, clsW, clsb, out, 3, Dc, 3, 1.0f, 0);
}